// round 1
// baseline (speedup 1.0000x reference)
#include <cuda_runtime.h>
#include <cuda_bf16.h>
#include <math.h>

#define B_DIM 1024
#define V_DIM 50257
#define E_DIM 128

// Scratch (no allocations allowed in kernel_launch)
__device__ int   g_ids[B_DIM];
__device__ float g_q[B_DIM * E_DIM];
__device__ float g_lse[B_DIM];

// ---------------------------------------------------------------------------
// Kernel 1: find the one-hot index per row of xs. Exactly one nonzero per row.
// ---------------------------------------------------------------------------
__global__ void find_ids_kernel(const float* __restrict__ xs, int V) {
    int b = blockIdx.x;
    const float* row = xs + (size_t)b * V;
    for (int v = threadIdx.x; v < V; v += blockDim.x) {
        if (row[v] != 0.0f) g_ids[b] = v;
    }
}

// ---------------------------------------------------------------------------
// Kernel 2: Q[b][j] = sum_e EMBEDM[id[b]][e] * metric[e][j]
// one block per row b, 128 threads (one per j)
// ---------------------------------------------------------------------------
__global__ void gather_project_kernel(const float* __restrict__ EMBEDM,
                                      const float* __restrict__ metric) {
    __shared__ float s[E_DIM];
    int b = blockIdx.x;
    int j = threadIdx.x;
    int id = g_ids[b];
    s[j] = EMBEDM[(size_t)id * E_DIM + j];
    __syncthreads();
    float acc = 0.0f;
#pragma unroll 16
    for (int e = 0; e < E_DIM; e++) {
        acc += s[e] * metric[e * E_DIM + j];
    }
    g_q[b * E_DIM + j] = acc;
}

// ---------------------------------------------------------------------------
// Kernel 3: scores = Q[1024,128] @ NEG[50257,128]^T  (NT gemm), write to C.
// BM=128, BN=64, BK=32, 256 threads, 8x4 micro-tile per thread.
// ---------------------------------------------------------------------------
#define BM 128
#define BN 64
#define BK 32
#define TM 8
#define TN 4

__global__ __launch_bounds__(256) void gemm_nt_kernel(
        const float* __restrict__ Nmat,  // [V, 128]
        float* __restrict__ C,           // [B, V]
        int V) {
    __shared__ __align__(16) float As[BK][BM];      // [k][m]
    __shared__ __align__(16) float Bs[BK][BN + 1];  // [k][n], +1 pad for STS conflicts

    const int tid = threadIdx.x;
    const int bm = blockIdx.y * BM;
    const int bn = blockIdx.x * BN;
    const int tm = (tid >> 4) * TM;   // 0..120
    const int tn = (tid & 15) * TN;   // 0..60

    float acc[TM][TN];
#pragma unroll
    for (int i = 0; i < TM; i++)
#pragma unroll
        for (int j = 0; j < TN; j++) acc[i][j] = 0.0f;

    for (int k0 = 0; k0 < E_DIM; k0 += BK) {
        // ---- load A tile (from g_q, tiny & L2-hot): BM*BK = 4096 floats ----
        // mapping keeps m contiguous within a warp so STS is conflict-free.
#pragma unroll
        for (int t = 0; t < 4; t++) {
            int idx = tid + t * 256;        // 0..1023
            int m   = idx & 127;            // 0..127
            int k4  = idx >> 7;             // 0..7
            const float4 v = *reinterpret_cast<const float4*>(
                &g_q[(size_t)(bm + m) * E_DIM + k0 + k4 * 4]);
            As[k4 * 4 + 0][m] = v.x;
            As[k4 * 4 + 1][m] = v.y;
            As[k4 * 4 + 2][m] = v.z;
            As[k4 * 4 + 3][m] = v.w;
        }
        // ---- load B tile (NEG, the big stream): coalesced 128B rows ----
#pragma unroll
        for (int t = 0; t < 2; t++) {
            int idx = tid + t * 256;        // 0..511
            int kq  = idx & 7;              // float4 index in k-tile
            int n   = idx >> 3;             // 0..63
            int gn  = bn + n;
            float4 v;
            if (gn < V) {
                v = *reinterpret_cast<const float4*>(
                    &Nmat[(size_t)gn * E_DIM + k0 + kq * 4]);
            } else {
                v = make_float4(0.f, 0.f, 0.f, 0.f);
            }
            Bs[kq * 4 + 0][n] = v.x;
            Bs[kq * 4 + 1][n] = v.y;
            Bs[kq * 4 + 2][n] = v.z;
            Bs[kq * 4 + 3][n] = v.w;
        }
        __syncthreads();

#pragma unroll
        for (int k = 0; k < BK; k++) {
            float a[TM];
            float b[TN];
            *reinterpret_cast<float4*>(&a[0]) =
                *reinterpret_cast<const float4*>(&As[k][tm]);
            *reinterpret_cast<float4*>(&a[4]) =
                *reinterpret_cast<const float4*>(&As[k][tm + 4]);
#pragma unroll
            for (int j = 0; j < TN; j++) b[j] = Bs[k][tn + j];
#pragma unroll
            for (int i = 0; i < TM; i++)
#pragma unroll
                for (int j = 0; j < TN; j++)
                    acc[i][j] += a[i] * b[j];
        }
        __syncthreads();
    }

    // ---- store ----
#pragma unroll
    for (int i = 0; i < TM; i++) {
        const size_t rowoff = (size_t)(bm + tm + i) * V + bn + tn;
#pragma unroll
        for (int j = 0; j < TN; j++) {
            int gn = bn + tn + j;
            if (gn < V) C[rowoff + j] = acc[i][j];
        }
    }
}

// ---------------------------------------------------------------------------
// Kernel 4: per-row online logsumexp over V. One block per row.
// ---------------------------------------------------------------------------
__global__ void row_lse_kernel(const float* __restrict__ C, int V) {
    const int b = blockIdx.x;
    const int tid = threadIdx.x;
    const float* row = C + (size_t)b * V;

    float m = -INFINITY;
    float s = 0.0f;
    for (int v = tid; v < V; v += blockDim.x) {
        float x = row[v];
        if (x > m) {
            s = s * __expf(m - x) + 1.0f;
            m = x;
        } else {
            s += __expf(x - m);
        }
    }

    __shared__ float sm[256];
    __shared__ float ss[256];
    sm[tid] = m;
    ss[tid] = s;
    __syncthreads();
    for (int o = 128; o > 0; o >>= 1) {
        if (tid < o) {
            float m2 = sm[tid + o], s2 = ss[tid + o];
            float m1 = sm[tid],     s1 = ss[tid];
            float M = fmaxf(m1, m2);
            ss[tid] = s1 * __expf(m1 - M) + s2 * __expf(m2 - M);
            sm[tid] = M;
        }
        __syncthreads();
    }
    if (tid == 0) g_lse[b] = sm[0] + logf(ss[0]);
}

// ---------------------------------------------------------------------------
// Kernel 5: out[b][v] -= lse[b]
// ---------------------------------------------------------------------------
__global__ void sub_lse_kernel(float* __restrict__ C, int V) {
    const int b = blockIdx.y;
    const int v = blockIdx.x * blockDim.x + threadIdx.x;
    if (v < V) {
        C[(size_t)b * V + v] -= g_lse[b];
    }
}

// ---------------------------------------------------------------------------
extern "C" void kernel_launch(void* const* d_in, const int* in_sizes, int n_in,
                              void* d_out, int out_size) {
    const float* xs     = (const float*)d_in[0];  // [B, V]
    const float* metric = (const float*)d_in[1];  // [E, E]
    const float* EMBEDM = (const float*)d_in[2];  // [V, E]
    const float* NEG    = (const float*)d_in[3];  // [V, E]
    float* out = (float*)d_out;                   // [B, V]

    const int V = V_DIM;

    find_ids_kernel<<<B_DIM, 256>>>(xs, V);
    gather_project_kernel<<<B_DIM, E_DIM>>>(EMBEDM, metric);

    dim3 ggrid((V + BN - 1) / BN, B_DIM / BM);
    gemm_nt_kernel<<<ggrid, 256>>>(NEG, out, V);

    row_lse_kernel<<<B_DIM, 256>>>(out, V);

    dim3 sgrid((V + 255) / 256, B_DIM);
    sub_lse_kernel<<<sgrid, 256>>>(out, V);
}

// round 4
// speedup vs baseline: 1.9043x; 1.9043x over previous
#include <cuda_runtime.h>
#include <cuda_bf16.h>
#include <math.h>
#include <stdint.h>

#define B_DIM 1024
#define V_DIM 50257
#define E_DIM 128
#define NB    393          // ceil(V/128)
#define N4    12865792u    // B*V/4

// ---------------- scratch ----------------
__device__ int   g_ids[B_DIM];
__device__ float g_q[B_DIM * E_DIM];
__device__ float g_lse[B_DIM];
__device__ __align__(16) __nv_bfloat16 g_qhi[B_DIM * E_DIM];
__device__ __align__(16) __nv_bfloat16 g_qlo[B_DIM * E_DIM];
__device__ __align__(16) __nv_bfloat16 g_nhi[V_DIM * E_DIM];
__device__ __align__(16) __nv_bfloat16 g_nlo[V_DIM * E_DIM];
__device__ float g_pmax[B_DIM * NB];
__device__ float g_psum[B_DIM * NB];

// ---------------- helpers ----------------
__device__ __forceinline__ uint32_t smem_u32(const void* p) {
    uint32_t a;
    asm("{ .reg .u64 t; cvta.to.shared.u64 t, %1; cvt.u32.u64 %0, t; }" : "=r"(a) : "l"(p));
    return a;
}
__device__ __forceinline__ void ldmatrix_x4(uint32_t* r, uint32_t addr) {
    asm volatile("ldmatrix.sync.aligned.m8n8.x4.shared.b16 {%0,%1,%2,%3}, [%4];"
                 : "=r"(r[0]), "=r"(r[1]), "=r"(r[2]), "=r"(r[3]) : "r"(addr));
}
__device__ __forceinline__ void ldmatrix_x2(uint32_t* r, uint32_t addr) {
    asm volatile("ldmatrix.sync.aligned.m8n8.x2.shared.b16 {%0,%1}, [%2];"
                 : "=r"(r[0]), "=r"(r[1]) : "r"(addr));
}
__device__ __forceinline__ void mma16816(float* d, const uint32_t* a, const uint32_t* b) {
    asm volatile(
        "mma.sync.aligned.m16n8k16.row.col.f32.bf16.bf16.f32 "
        "{%0,%1,%2,%3}, {%4,%5,%6,%7}, {%8,%9}, {%0,%1,%2,%3};"
        : "+f"(d[0]), "+f"(d[1]), "+f"(d[2]), "+f"(d[3])
        : "r"(a[0]), "r"(a[1]), "r"(a[2]), "r"(a[3]), "r"(b[0]), "r"(b[1]));
}

// smem layout (bytes)
#define OFF_AHI  0
#define OFF_ALO  16384
#define OFF_BHI  32768
#define OFF_BLO  65536
#define OFF_SMAX 98304
#define OFF_SSUM 99328
#define SMEM_TOTAL 100352

// ---------------------------------------------------------------------------
// Kernel 1: find one-hot ids (flat float4)
// ---------------------------------------------------------------------------
__global__ void find_ids_kernel(const float4* __restrict__ xs) {
    unsigned i = blockIdx.x * 256u + threadIdx.x;     // < N4
    float4 v = xs[i];
    if (v.x != 0.f || v.y != 0.f || v.z != 0.f || v.w != 0.f) {
        unsigned base = i * 4u;
        if (v.x != 0.f) g_ids[ base      / V_DIM] =  base      % V_DIM;
        if (v.y != 0.f) g_ids[(base + 1) / V_DIM] = (base + 1) % V_DIM;
        if (v.z != 0.f) g_ids[(base + 2) / V_DIM] = (base + 2) % V_DIM;
        if (v.w != 0.f) g_ids[(base + 3) / V_DIM] = (base + 3) % V_DIM;
    }
}

// ---------------------------------------------------------------------------
// Kernel 2: Q[b][j] = sum_e EMBEDM[id[b]][e] * metric[e][j]
// ---------------------------------------------------------------------------
__global__ void gather_project_kernel(const float* __restrict__ EMBEDM,
                                      const float* __restrict__ metric) {
    __shared__ float s[E_DIM];
    int b = blockIdx.x, j = threadIdx.x;
    int id = g_ids[b];
    s[j] = EMBEDM[(size_t)id * E_DIM + j];
    __syncthreads();
    float acc = 0.0f;
#pragma unroll 16
    for (int e = 0; e < E_DIM; e++) acc += s[e] * metric[e * E_DIM + j];
    g_q[b * E_DIM + j] = acc;
}

// ---------------------------------------------------------------------------
// Kernel 3: bf16 hi/lo split conversions
// ---------------------------------------------------------------------------
__global__ void convert_q_kernel() {
    int i = blockIdx.x * 256 + threadIdx.x;
    if (i < B_DIM * E_DIM) {
        float x = g_q[i];
        __nv_bfloat16 h = __float2bfloat16(x);
        g_qhi[i] = h;
        g_qlo[i] = __float2bfloat16(x - __bfloat162float(h));
    }
}
__global__ void convert_neg_kernel(const float* __restrict__ NEG) {
    int i = blockIdx.x * 256 + threadIdx.x;
    if (i < V_DIM * E_DIM) {
        float x = NEG[i];
        __nv_bfloat16 h = __float2bfloat16(x);
        g_nhi[i] = h;
        g_nlo[i] = __float2bfloat16(x - __bfloat162float(h));
    }
}

// ---------------------------------------------------------------------------
// Kernel 4: HMMA (mma.sync bf16, 3-term split) GEMM + fused partial LSE.
// grid = (393, 16). CTA tile: M=64, N=128. 8 warps as 2(M) x 4(N), 32x32 each.
// ---------------------------------------------------------------------------
__global__ void __launch_bounds__(256, 2) gemm_hmma_kernel(float* __restrict__ C) {
    extern __shared__ __align__(1024) char smem[];
    const uint32_t sb = smem_u32(smem);
    const int tid = threadIdx.x;
    const int lane = tid & 31;
    const int wid = tid >> 5;
    const int bn = blockIdx.x * 128;
    const int bm = blockIdx.y * 64;

    // ---- load A tiles (64 rows x 128 k, hi/lo), xor-swizzled 16B chunks ----
#pragma unroll
    for (int i = 0; i < 4; i++) {
        int idx = tid + i * 256;          // 0..1023
        int r = idx >> 4, c = idx & 15;
        uint32_t off = (uint32_t)((r << 8) + ((c ^ (r & 7)) << 4));
        *reinterpret_cast<uint4*>(smem + OFF_AHI + off) =
            *reinterpret_cast<const uint4*>(&g_qhi[(size_t)(bm + r) * E_DIM + c * 8]);
        *reinterpret_cast<uint4*>(smem + OFF_ALO + off) =
            *reinterpret_cast<const uint4*>(&g_qlo[(size_t)(bm + r) * E_DIM + c * 8]);
    }
    // ---- load B tiles (128 rows x 128 k, hi/lo) ----
#pragma unroll
    for (int i = 0; i < 8; i++) {
        int idx = tid + i * 256;          // 0..2047
        int r = idx >> 4, c = idx & 15;
        int gn = bn + r;
        uint4 vh = make_uint4(0, 0, 0, 0), vl = make_uint4(0, 0, 0, 0);
        if (gn < V_DIM) {
            vh = *reinterpret_cast<const uint4*>(&g_nhi[(size_t)gn * E_DIM + c * 8]);
            vl = *reinterpret_cast<const uint4*>(&g_nlo[(size_t)gn * E_DIM + c * 8]);
        }
        uint32_t off = (uint32_t)((r << 8) + ((c ^ (r & 7)) << 4));
        *reinterpret_cast<uint4*>(smem + OFF_BHI + off) = vh;
        *reinterpret_cast<uint4*>(smem + OFF_BLO + off) = vl;
    }
    __syncthreads();

    const int wm = (wid >> 2) * 32;
    const int wn = (wid & 3) * 32;

    float acc[2][4][4];
#pragma unroll
    for (int mf = 0; mf < 2; mf++)
#pragma unroll
        for (int nf = 0; nf < 4; nf++)
#pragma unroll
            for (int k = 0; k < 4; k++) acc[mf][nf][k] = 0.0f;

    // per-thread ldmatrix address precompute
    const int i8  = lane & 7;
    const int q   = lane >> 3;           // 0..3
    const int qhi = q >> 1;              // A: k-chunk-half select
    const int q2  = q & 1;               // B: k-chunk-half select (x2 uses lanes 0-15)
    uint32_t a_rowoff[2];
    int a7[2];
#pragma unroll
    for (int mf = 0; mf < 2; mf++) {
        int ar = wm + mf * 16 + i8 + ((q & 1) << 3);
        a_rowoff[mf] = (uint32_t)(ar << 8);
        a7[mf] = ar & 7;
    }
    uint32_t b_rowoff[4];
    int b7[4];
#pragma unroll
    for (int nf = 0; nf < 4; nf++) {
        int br = wn + nf * 8 + i8;
        b_rowoff[nf] = (uint32_t)(br << 8);
        b7[nf] = br & 7;
    }

    // 3 terms: (Ahi,Bhi), (Alo,Bhi), (Ahi,Blo)
#pragma unroll
    for (int t = 0; t < 3; t++) {
        const uint32_t aB = sb + (t == 1 ? OFF_ALO : OFF_AHI);
        const uint32_t bB = sb + (t == 2 ? OFF_BLO : OFF_BHI);
#pragma unroll
        for (int kk = 0; kk < 8; kk++) {
            uint32_t a[2][4];
#pragma unroll
            for (int mf = 0; mf < 2; mf++) {
                uint32_t ad = aB + a_rowoff[mf] +
                    (uint32_t)(((kk * 2 + qhi) ^ a7[mf]) << 4);
                ldmatrix_x4(a[mf], ad);
            }
            uint32_t b[4][2];
#pragma unroll
            for (int nf = 0; nf < 4; nf++) {
                uint32_t bd = bB + b_rowoff[nf] +
                    (uint32_t)(((kk * 2 + q2) ^ b7[nf]) << 4);
                ldmatrix_x2(b[nf], bd);
            }
#pragma unroll
            for (int mf = 0; mf < 2; mf++)
#pragma unroll
                for (int nf = 0; nf < 4; nf++)
                    mma16816(acc[mf][nf], a[mf], b[nf]);
        }
    }

    // ---- epilogue: store C (scalar stores — V_DIM odd breaks 8B alignment)
    //      + fused partial LSE ----
    const int r_in = lane >> 2;          // 0..7
    const int cp   = lane & 3;           // col-pair
    const int wni  = wid & 3;
    float* smax = (float*)(smem + OFF_SMAX);   // [64][4]
    float* ssum = (float*)(smem + OFF_SSUM);   // [64][4]

    bool cv[4][2];
#pragma unroll
    for (int nf = 0; nf < 4; nf++)
#pragma unroll
        for (int j = 0; j < 2; j++)
            cv[nf][j] = (bn + wn + nf * 8 + cp * 2 + j) < V_DIM;

    // store + local row max
#pragma unroll
    for (int mf = 0; mf < 2; mf++) {
#pragma unroll
        for (int h = 0; h < 2; h++) {
            int tr  = wm + mf * 16 + h * 8 + r_in;       // tile row 0..63
            int row = bm + tr;
            float m = -INFINITY;
            const size_t rowbase = (size_t)row * V_DIM;
#pragma unroll
            for (int nf = 0; nf < 4; nf++) {
                float v0 = acc[mf][nf][h * 2 + 0];
                float v1 = acc[mf][nf][h * 2 + 1];
                int col = bn + wn + nf * 8 + cp * 2;
                if (cv[nf][0]) { C[rowbase + col] = v0;     m = fmaxf(m, v0); }
                if (cv[nf][1]) { C[rowbase + col + 1] = v1; m = fmaxf(m, v1); }
            }
            m = fmaxf(m, __shfl_xor_sync(0xFFFFFFFF, m, 1));
            m = fmaxf(m, __shfl_xor_sync(0xFFFFFFFF, m, 2));
            if (cp == 0) smax[tr * 4 + wni] = m;
        }
    }
    __syncthreads();

#pragma unroll
    for (int mf = 0; mf < 2; mf++) {
#pragma unroll
        for (int h = 0; h < 2; h++) {
            int tr = wm + mf * 16 + h * 8 + r_in;
            float g = fmaxf(fmaxf(smax[tr * 4 + 0], smax[tr * 4 + 1]),
                            fmaxf(smax[tr * 4 + 2], smax[tr * 4 + 3]));
            float s = 0.0f;
#pragma unroll
            for (int nf = 0; nf < 4; nf++) {
                if (cv[nf][0]) s += __expf(acc[mf][nf][h * 2 + 0] - g);
                if (cv[nf][1]) s += __expf(acc[mf][nf][h * 2 + 1] - g);
            }
            s += __shfl_xor_sync(0xFFFFFFFF, s, 1);
            s += __shfl_xor_sync(0xFFFFFFFF, s, 2);
            if (cp == 0) ssum[tr * 4 + wni] = s;
        }
    }
    __syncthreads();

    if (tid < 64) {
        float g = fmaxf(fmaxf(smax[tid * 4 + 0], smax[tid * 4 + 1]),
                        fmaxf(smax[tid * 4 + 2], smax[tid * 4 + 3]));
        float s = ssum[tid * 4 + 0] + ssum[tid * 4 + 1] +
                  ssum[tid * 4 + 2] + ssum[tid * 4 + 3];
        g_pmax[(size_t)(bm + tid) * NB + blockIdx.x] = g;
        g_psum[(size_t)(bm + tid) * NB + blockIdx.x] = s;
    }
}

// ---------------------------------------------------------------------------
// Kernel 5: reduce partial (max,sum) -> lse per row
// ---------------------------------------------------------------------------
__global__ void reduce_lse_kernel() {
    int b = blockIdx.x;
    int t = threadIdx.x;        // 128
    float m = -INFINITY, s = 0.0f;
    for (int i = t; i < NB; i += 128) {
        float pm = g_pmax[(size_t)b * NB + i];
        float ps = g_psum[(size_t)b * NB + i];
        if (pm > m) { s = s * __expf(m - pm) + ps; m = pm; }
        else        { s += ps * __expf(pm - m); }
    }
#pragma unroll
    for (int o = 16; o > 0; o >>= 1) {
        float m2 = __shfl_xor_sync(0xFFFFFFFF, m, o);
        float s2 = __shfl_xor_sync(0xFFFFFFFF, s, o);
        float M = fmaxf(m, m2);
        s = s * __expf(m - M) + s2 * __expf(m2 - M);
        m = M;
    }
    __shared__ float sm[4], ss[4];
    if ((t & 31) == 0) { sm[t >> 5] = m; ss[t >> 5] = s; }
    __syncthreads();
    if (t == 0) {
        m = sm[0]; s = ss[0];
#pragma unroll
        for (int w = 1; w < 4; w++) {
            float M = fmaxf(m, sm[w]);
            s = s * __expf(m - M) + ss[w] * __expf(sm[w] - M);
            m = M;
        }
        g_lse[b] = m + logf(s);
    }
}

// ---------------------------------------------------------------------------
// Kernel 6: out -= lse[row]  (flat float4)
// ---------------------------------------------------------------------------
__global__ void sub_lse_kernel(float4* __restrict__ C) {
    unsigned i = blockIdx.x * 256u + threadIdx.x;   // < N4
    float4 v = C[i];
    unsigned base = i * 4u;
    v.x -= g_lse[ base      / V_DIM];
    v.y -= g_lse[(base + 1) / V_DIM];
    v.z -= g_lse[(base + 2) / V_DIM];
    v.w -= g_lse[(base + 3) / V_DIM];
    C[i] = v;
}

// ---------------------------------------------------------------------------
extern "C" void kernel_launch(void* const* d_in, const int* in_sizes, int n_in,
                              void* d_out, int out_size) {
    const float* xs     = (const float*)d_in[0];
    const float* metric = (const float*)d_in[1];
    const float* EMBEDM = (const float*)d_in[2];
    const float* NEG    = (const float*)d_in[3];
    float* out = (float*)d_out;

    cudaFuncSetAttribute(gemm_hmma_kernel,
                         cudaFuncAttributeMaxDynamicSharedMemorySize, SMEM_TOTAL);

    find_ids_kernel<<<N4 / 256, 256>>>((const float4*)xs);
    gather_project_kernel<<<B_DIM, E_DIM>>>(EMBEDM, metric);
    convert_q_kernel<<<(B_DIM * E_DIM + 255) / 256, 256>>>();
    convert_neg_kernel<<<(V_DIM * E_DIM + 255) / 256, 256>>>(NEG);

    gemm_hmma_kernel<<<dim3(NB, 16), 256, SMEM_TOTAL>>>(out);

    reduce_lse_kernel<<<B_DIM, 128>>>();
    sub_lse_kernel<<<N4 / 256, 256>>>((float4*)out);
}

// round 5
// speedup vs baseline: 2.3126x; 1.2144x over previous
#include <cuda_runtime.h>
#include <cuda_bf16.h>
#include <math.h>
#include <stdint.h>

#define B_DIM 1024
#define V_DIM 50257
#define E_DIM 128
#define NB    393          // ceil(V/128)
#define N4    12865792u    // B*V/4

// ---------------- scratch ----------------
__device__ int   g_ids[B_DIM];
__device__ float g_lse[B_DIM];
__device__ __align__(16) __nv_bfloat16 g_qhi[B_DIM * E_DIM];
__device__ __align__(16) __nv_bfloat16 g_qlo[B_DIM * E_DIM];
__device__ __align__(16) __nv_bfloat16 g_nhi[V_DIM * E_DIM];
__device__ __align__(16) __nv_bfloat16 g_nlo[V_DIM * E_DIM];
__device__ float g_pmax[B_DIM * NB];
__device__ float g_psum[B_DIM * NB];

// ---------------- helpers ----------------
__device__ __forceinline__ uint32_t smem_u32(const void* p) {
    uint32_t a;
    asm("{ .reg .u64 t; cvta.to.shared.u64 t, %1; cvt.u32.u64 %0, t; }" : "=r"(a) : "l"(p));
    return a;
}
__device__ __forceinline__ void ldmatrix_x4(uint32_t* r, uint32_t addr) {
    asm volatile("ldmatrix.sync.aligned.m8n8.x4.shared.b16 {%0,%1,%2,%3}, [%4];"
                 : "=r"(r[0]), "=r"(r[1]), "=r"(r[2]), "=r"(r[3]) : "r"(addr));
}
__device__ __forceinline__ void ldmatrix_x2(uint32_t* r, uint32_t addr) {
    asm volatile("ldmatrix.sync.aligned.m8n8.x2.shared.b16 {%0,%1}, [%2];"
                 : "=r"(r[0]), "=r"(r[1]) : "r"(addr));
}
__device__ __forceinline__ void mma16816(float* d, const uint32_t* a, const uint32_t* b) {
    asm volatile(
        "mma.sync.aligned.m16n8k16.row.col.f32.bf16.bf16.f32 "
        "{%0,%1,%2,%3}, {%4,%5,%6,%7}, {%8,%9}, {%0,%1,%2,%3};"
        : "+f"(d[0]), "+f"(d[1]), "+f"(d[2]), "+f"(d[3])
        : "r"(a[0]), "r"(a[1]), "r"(a[2]), "r"(a[3]), "r"(b[0]), "r"(b[1]));
}

// smem layout (bytes)
#define OFF_AHI  0
#define OFF_ALO  16384
#define OFF_BHI  32768
#define OFF_BLO  65536
#define OFF_SMAX 98304
#define OFF_SSUM 99328
#define SMEM_TOTAL 100352

// ---------------------------------------------------------------------------
// Kernel 1: find one-hot ids (flat float4)
// ---------------------------------------------------------------------------
__global__ void find_ids_kernel(const float4* __restrict__ xs) {
    unsigned i = blockIdx.x * 256u + threadIdx.x;     // < N4
    float4 v = xs[i];
    if (v.x != 0.f || v.y != 0.f || v.z != 0.f || v.w != 0.f) {
        unsigned base = i * 4u;
        if (v.x != 0.f) g_ids[ base      / V_DIM] =  base      % V_DIM;
        if (v.y != 0.f) g_ids[(base + 1) / V_DIM] = (base + 1) % V_DIM;
        if (v.z != 0.f) g_ids[(base + 2) / V_DIM] = (base + 2) % V_DIM;
        if (v.w != 0.f) g_ids[(base + 3) / V_DIM] = (base + 3) % V_DIM;
    }
}

// ---------------------------------------------------------------------------
// Kernel 2: gather + project + hi/lo split, fused.
// Q[b][j] = sum_e EMBEDM[id[b]][e] * metric[e][j]; write qhi/qlo.
// ---------------------------------------------------------------------------
__global__ void gather_project_kernel(const float* __restrict__ EMBEDM,
                                      const float* __restrict__ metric) {
    __shared__ float s[E_DIM];
    int b = blockIdx.x, j = threadIdx.x;
    int id = g_ids[b];
    s[j] = EMBEDM[(size_t)id * E_DIM + j];
    __syncthreads();
    float acc = 0.0f;
#pragma unroll 16
    for (int e = 0; e < E_DIM; e++) acc += s[e] * metric[e * E_DIM + j];
    __nv_bfloat16 h = __float2bfloat16(acc);
    g_qhi[b * E_DIM + j] = h;
    g_qlo[b * E_DIM + j] = __float2bfloat16(acc - __bfloat162float(h));
}

// ---------------------------------------------------------------------------
// Kernel 3: NEG hi/lo split conversion
// ---------------------------------------------------------------------------
__global__ void convert_neg_kernel(const float* __restrict__ NEG) {
    int i = blockIdx.x * 256 + threadIdx.x;
    if (i < V_DIM * E_DIM) {
        float x = __ldcs(&NEG[i]);
        __nv_bfloat16 h = __float2bfloat16(x);
        g_nhi[i] = h;
        g_nlo[i] = __float2bfloat16(x - __bfloat162float(h));
    }
}

// ---------------------------------------------------------------------------
// Kernel 4: HMMA (mma.sync bf16, 3-term split) GEMM + fused partial LSE.
// grid = (393, 8). CTA: N=128 (bn), loops over 2 M-tiles of 64 rows.
// B tile loaded to smem ONCE per CTA. 8 warps as 2(M) x 4(N), 32x32 each.
// ---------------------------------------------------------------------------
__global__ void __launch_bounds__(256, 2) gemm_hmma_kernel(float* __restrict__ C) {
    extern __shared__ __align__(1024) char smem[];
    const uint32_t sb = smem_u32(smem);
    const int tid = threadIdx.x;
    const int lane = tid & 31;
    const int wid = tid >> 5;
    const int bn = blockIdx.x * 128;

    // ---- load B tiles (128 rows x 128 k, hi/lo), once per CTA ----
#pragma unroll
    for (int i = 0; i < 8; i++) {
        int idx = tid + i * 256;          // 0..2047
        int r = idx >> 4, c = idx & 15;
        int gn = bn + r;
        uint4 vh = make_uint4(0, 0, 0, 0), vl = make_uint4(0, 0, 0, 0);
        if (gn < V_DIM) {
            vh = *reinterpret_cast<const uint4*>(&g_nhi[(size_t)gn * E_DIM + c * 8]);
            vl = *reinterpret_cast<const uint4*>(&g_nlo[(size_t)gn * E_DIM + c * 8]);
        }
        uint32_t off = (uint32_t)((r << 8) + ((c ^ (r & 7)) << 4));
        *reinterpret_cast<uint4*>(smem + OFF_BHI + off) = vh;
        *reinterpret_cast<uint4*>(smem + OFF_BLO + off) = vl;
    }

    const int wm = (wid >> 2) * 32;
    const int wn = (wid & 3) * 32;

    // per-thread ldmatrix address precompute
    const int i8  = lane & 7;
    const int q   = lane >> 3;           // 0..3
    const int qhi = q >> 1;              // A: k-chunk-half select
    const int q2  = q & 1;               // B: k-chunk-half select
    uint32_t a_rowoff[2];
    int a7[2];
#pragma unroll
    for (int mf = 0; mf < 2; mf++) {
        int ar = wm + mf * 16 + i8 + ((q & 1) << 3);
        a_rowoff[mf] = (uint32_t)(ar << 8);
        a7[mf] = ar & 7;
    }
    uint32_t b_rowoff[4];
    int b7[4];
#pragma unroll
    for (int nf = 0; nf < 4; nf++) {
        int br = wn + nf * 8 + i8;
        b_rowoff[nf] = (uint32_t)(br << 8);
        b7[nf] = br & 7;
    }

    // epilogue constants
    const int r_in = lane >> 2;          // 0..7
    const int cp   = lane & 3;           // col-pair
    const int wni  = wid & 3;
    float* smax = (float*)(smem + OFF_SMAX);   // [64][4]
    float* ssum = (float*)(smem + OFF_SSUM);   // [64][4]
    bool cv[4][2];
#pragma unroll
    for (int nf = 0; nf < 4; nf++)
#pragma unroll
        for (int j = 0; j < 2; j++)
            cv[nf][j] = (bn + wn + nf * 8 + cp * 2 + j) < V_DIM;

    for (int mt = 0; mt < 2; mt++) {
        const int bm = (blockIdx.y * 2 + mt) * 64;

        // ---- load A tiles (64 rows x 128 k, hi/lo) ----
#pragma unroll
        for (int i = 0; i < 4; i++) {
            int idx = tid + i * 256;          // 0..1023
            int r = idx >> 4, c = idx & 15;
            uint32_t off = (uint32_t)((r << 8) + ((c ^ (r & 7)) << 4));
            *reinterpret_cast<uint4*>(smem + OFF_AHI + off) =
                *reinterpret_cast<const uint4*>(&g_qhi[(size_t)(bm + r) * E_DIM + c * 8]);
            *reinterpret_cast<uint4*>(smem + OFF_ALO + off) =
                *reinterpret_cast<const uint4*>(&g_qlo[(size_t)(bm + r) * E_DIM + c * 8]);
        }
        __syncthreads();

        float acc[2][4][4];
#pragma unroll
        for (int mf = 0; mf < 2; mf++)
#pragma unroll
            for (int nf = 0; nf < 4; nf++)
#pragma unroll
                for (int k = 0; k < 4; k++) acc[mf][nf][k] = 0.0f;

        // ---- mainloop: load all fragments once per kk, 24 mmas ----
#pragma unroll
        for (int kk = 0; kk < 8; kk++) {
            uint32_t ah[2][4], al[2][4];
#pragma unroll
            for (int mf = 0; mf < 2; mf++) {
                uint32_t chunk = (uint32_t)(((kk * 2 + qhi) ^ a7[mf]) << 4);
                ldmatrix_x4(ah[mf], sb + OFF_AHI + a_rowoff[mf] + chunk);
                ldmatrix_x4(al[mf], sb + OFF_ALO + a_rowoff[mf] + chunk);
            }
            uint32_t bh[4][2], bl[4][2];
#pragma unroll
            for (int nf = 0; nf < 4; nf++) {
                uint32_t chunk = (uint32_t)(((kk * 2 + q2) ^ b7[nf]) << 4);
                ldmatrix_x2(bh[nf], sb + OFF_BHI + b_rowoff[nf] + chunk);
                ldmatrix_x2(bl[nf], sb + OFF_BLO + b_rowoff[nf] + chunk);
            }
            // term 1: Ahi * Bhi
#pragma unroll
            for (int mf = 0; mf < 2; mf++)
#pragma unroll
                for (int nf = 0; nf < 4; nf++)
                    mma16816(acc[mf][nf], ah[mf], bh[nf]);
            // term 2: Alo * Bhi
#pragma unroll
            for (int mf = 0; mf < 2; mf++)
#pragma unroll
                for (int nf = 0; nf < 4; nf++)
                    mma16816(acc[mf][nf], al[mf], bh[nf]);
            // term 3: Ahi * Blo
#pragma unroll
            for (int mf = 0; mf < 2; mf++)
#pragma unroll
                for (int nf = 0; nf < 4; nf++)
                    mma16816(acc[mf][nf], ah[mf], bl[nf]);
        }

        // ---- epilogue: store C (streaming, scalar: V_DIM odd) + partial LSE ----
#pragma unroll
        for (int mf = 0; mf < 2; mf++) {
#pragma unroll
            for (int h = 0; h < 2; h++) {
                int tr  = wm + mf * 16 + h * 8 + r_in;       // tile row 0..63
                int row = bm + tr;
                float m = -INFINITY;
                const size_t rowbase = (size_t)row * V_DIM;
#pragma unroll
                for (int nf = 0; nf < 4; nf++) {
                    float v0 = acc[mf][nf][h * 2 + 0];
                    float v1 = acc[mf][nf][h * 2 + 1];
                    int col = bn + wn + nf * 8 + cp * 2;
                    if (cv[nf][0]) { __stcs(&C[rowbase + col], v0);     m = fmaxf(m, v0); }
                    if (cv[nf][1]) { __stcs(&C[rowbase + col + 1], v1); m = fmaxf(m, v1); }
                }
                m = fmaxf(m, __shfl_xor_sync(0xFFFFFFFF, m, 1));
                m = fmaxf(m, __shfl_xor_sync(0xFFFFFFFF, m, 2));
                if (cp == 0) smax[tr * 4 + wni] = m;
            }
        }
        __syncthreads();

#pragma unroll
        for (int mf = 0; mf < 2; mf++) {
#pragma unroll
            for (int h = 0; h < 2; h++) {
                int tr = wm + mf * 16 + h * 8 + r_in;
                float g = fmaxf(fmaxf(smax[tr * 4 + 0], smax[tr * 4 + 1]),
                                fmaxf(smax[tr * 4 + 2], smax[tr * 4 + 3]));
                float s = 0.0f;
#pragma unroll
                for (int nf = 0; nf < 4; nf++) {
                    if (cv[nf][0]) s += __expf(acc[mf][nf][h * 2 + 0] - g);
                    if (cv[nf][1]) s += __expf(acc[mf][nf][h * 2 + 1] - g);
                }
                s += __shfl_xor_sync(0xFFFFFFFF, s, 1);
                s += __shfl_xor_sync(0xFFFFFFFF, s, 2);
                if (cp == 0) ssum[tr * 4 + wni] = s;
            }
        }
        __syncthreads();

        if (tid < 64) {
            float g = fmaxf(fmaxf(smax[tid * 4 + 0], smax[tid * 4 + 1]),
                            fmaxf(smax[tid * 4 + 2], smax[tid * 4 + 3]));
            float s = ssum[tid * 4 + 0] + ssum[tid * 4 + 1] +
                      ssum[tid * 4 + 2] + ssum[tid * 4 + 3];
            g_pmax[(size_t)(bm + tid) * NB + blockIdx.x] = g;
            g_psum[(size_t)(bm + tid) * NB + blockIdx.x] = s;
        }
        __syncthreads();
    }
}

// ---------------------------------------------------------------------------
// Kernel 5: reduce partial (max,sum) -> lse per row
// ---------------------------------------------------------------------------
__global__ void reduce_lse_kernel() {
    int b = blockIdx.x;
    int t = threadIdx.x;        // 128
    float m = -INFINITY, s = 0.0f;
    for (int i = t; i < NB; i += 128) {
        float pm = g_pmax[(size_t)b * NB + i];
        float ps = g_psum[(size_t)b * NB + i];
        if (pm > m) { s = s * __expf(m - pm) + ps; m = pm; }
        else        { s += ps * __expf(pm - m); }
    }
#pragma unroll
    for (int o = 16; o > 0; o >>= 1) {
        float m2 = __shfl_xor_sync(0xFFFFFFFF, m, o);
        float s2 = __shfl_xor_sync(0xFFFFFFFF, s, o);
        float M = fmaxf(m, m2);
        s = s * __expf(m - M) + s2 * __expf(m2 - M);
        m = M;
    }
    __shared__ float sm[4], ss[4];
    if ((t & 31) == 0) { sm[t >> 5] = m; ss[t >> 5] = s; }
    __syncthreads();
    if (t == 0) {
        m = sm[0]; s = ss[0];
#pragma unroll
        for (int w = 1; w < 4; w++) {
            float M = fmaxf(m, sm[w]);
            s = s * __expf(m - M) + ss[w] * __expf(sm[w] - M);
            m = M;
        }
        g_lse[b] = m + logf(s);
    }
}

// ---------------------------------------------------------------------------
// Kernel 6: out -= lse[row]  (flat float4, streaming)
// ---------------------------------------------------------------------------
__global__ void sub_lse_kernel(float4* __restrict__ C) {
    unsigned i = blockIdx.x * 256u + threadIdx.x;   // < N4
    float4 v = __ldcs(&C[i]);
    unsigned base = i * 4u;
    v.x -= g_lse[ base      / V_DIM];
    v.y -= g_lse[(base + 1) / V_DIM];
    v.z -= g_lse[(base + 2) / V_DIM];
    v.w -= g_lse[(base + 3) / V_DIM];
    __stcs(&C[i], v);
}

// ---------------------------------------------------------------------------
extern "C" void kernel_launch(void* const* d_in, const int* in_sizes, int n_in,
                              void* d_out, int out_size) {
    const float* xs     = (const float*)d_in[0];
    const float* metric = (const float*)d_in[1];
    const float* EMBEDM = (const float*)d_in[2];
    const float* NEG    = (const float*)d_in[3];
    float* out = (float*)d_out;

    cudaFuncSetAttribute(gemm_hmma_kernel,
                         cudaFuncAttributeMaxDynamicSharedMemorySize, SMEM_TOTAL);

    find_ids_kernel<<<N4 / 256, 256>>>((const float4*)xs);
    gather_project_kernel<<<B_DIM, E_DIM>>>(EMBEDM, metric);
    convert_neg_kernel<<<(V_DIM * E_DIM + 255) / 256, 256>>>(NEG);

    gemm_hmma_kernel<<<dim3(NB, 8), 256, SMEM_TOTAL>>>(out);

    reduce_lse_kernel<<<B_DIM, 128>>>();
    sub_lse_kernel<<<N4 / 256, 256>>>((float4*)out);
}

// round 6
// speedup vs baseline: 2.3398x; 1.0118x over previous
#include <cuda_runtime.h>
#include <cuda_bf16.h>
#include <math.h>
#include <stdint.h>

#define B_DIM 1024
#define V_DIM 50257
#define E_DIM 128
#define NB    393          // ceil(V/128)
#define N4    12865792u    // B*V/4

// ---------------- scratch ----------------
__device__ int   g_ids[B_DIM];
__device__ float g_lse[B_DIM];
__device__ __align__(16) __nv_bfloat16 g_qhi[B_DIM * E_DIM];
__device__ __align__(16) __nv_bfloat16 g_qlo[B_DIM * E_DIM];
__device__ __align__(16) __nv_bfloat16 g_nhi[V_DIM * E_DIM];
__device__ __align__(16) __nv_bfloat16 g_nlo[V_DIM * E_DIM];
__device__ float g_pmax[B_DIM * NB];
__device__ float g_psum[B_DIM * NB];

// ---------------- helpers ----------------
__device__ __forceinline__ uint32_t smem_u32(const void* p) {
    uint32_t a;
    asm("{ .reg .u64 t; cvta.to.shared.u64 t, %1; cvt.u32.u64 %0, t; }" : "=r"(a) : "l"(p));
    return a;
}
__device__ __forceinline__ void ldmatrix_x4(uint32_t* r, uint32_t addr) {
    asm volatile("ldmatrix.sync.aligned.m8n8.x4.shared.b16 {%0,%1,%2,%3}, [%4];"
                 : "=r"(r[0]), "=r"(r[1]), "=r"(r[2]), "=r"(r[3]) : "r"(addr));
}
__device__ __forceinline__ void mma16816(float* d, const uint32_t* a, const uint32_t* b) {
    asm volatile(
        "mma.sync.aligned.m16n8k16.row.col.f32.bf16.bf16.f32 "
        "{%0,%1,%2,%3}, {%4,%5,%6,%7}, {%8,%9}, {%0,%1,%2,%3};"
        : "+f"(d[0]), "+f"(d[1]), "+f"(d[2]), "+f"(d[3])
        : "r"(a[0]), "r"(a[1]), "r"(a[2]), "r"(a[3]), "r"(b[0]), "r"(b[1]));
}

// smem layout (bytes)
#define OFF_AHI  0
#define OFF_ALO  16384
#define OFF_BHI  32768
#define OFF_BLO  65536
#define OFF_SMAX 98304
#define OFF_SSUM 99328
#define SMEM_TOTAL 100352

// ---------------------------------------------------------------------------
// Kernel 1: find one-hot ids (flat float4)
// ---------------------------------------------------------------------------
__global__ void find_ids_kernel(const float4* __restrict__ xs) {
    unsigned i = blockIdx.x * 256u + threadIdx.x;     // < N4
    float4 v = xs[i];
    if (v.x != 0.f || v.y != 0.f || v.z != 0.f || v.w != 0.f) {
        unsigned base = i * 4u;
        if (v.x != 0.f) g_ids[ base      / V_DIM] =  base      % V_DIM;
        if (v.y != 0.f) g_ids[(base + 1) / V_DIM] = (base + 1) % V_DIM;
        if (v.z != 0.f) g_ids[(base + 2) / V_DIM] = (base + 2) % V_DIM;
        if (v.w != 0.f) g_ids[(base + 3) / V_DIM] = (base + 3) % V_DIM;
    }
}

// ---------------------------------------------------------------------------
// Kernel 2: gather + project + hi/lo split, fused.
// ---------------------------------------------------------------------------
__global__ void gather_project_kernel(const float* __restrict__ EMBEDM,
                                      const float* __restrict__ metric) {
    __shared__ float s[E_DIM];
    int b = blockIdx.x, j = threadIdx.x;
    int id = g_ids[b];
    s[j] = EMBEDM[(size_t)id * E_DIM + j];
    __syncthreads();
    float acc = 0.0f;
#pragma unroll 16
    for (int e = 0; e < E_DIM; e++) acc += s[e] * metric[e * E_DIM + j];
    __nv_bfloat16 h = __float2bfloat16(acc);
    g_qhi[b * E_DIM + j] = h;
    g_qlo[b * E_DIM + j] = __float2bfloat16(acc - __bfloat162float(h));
}

// ---------------------------------------------------------------------------
// Kernel 3: NEG hi/lo split conversion
// ---------------------------------------------------------------------------
__global__ void convert_neg_kernel(const float* __restrict__ NEG) {
    int i = blockIdx.x * 256 + threadIdx.x;
    if (i < V_DIM * E_DIM) {
        float x = __ldcs(&NEG[i]);
        __nv_bfloat16 h = __float2bfloat16(x);
        g_nhi[i] = h;
        g_nlo[i] = __float2bfloat16(x - __bfloat162float(h));
    }
}

// ---------------------------------------------------------------------------
// Kernel 4: HMMA (mma.sync bf16, 3-term split) GEMM + fused partial LSE.
// grid = (393, 4). CTA: N=128 (bn), loops over 4 M-tiles of 64 rows.
// B tile in smem once per CTA. 8 warps as 2(M) x 4(N), 32x32 each.
// B fragments loaded pairwise with ldmatrix.x4 (8 LDSM / 24 HMMA per kk).
// ---------------------------------------------------------------------------
__global__ void __launch_bounds__(256, 2) gemm_hmma_kernel(float* __restrict__ C) {
    extern __shared__ __align__(1024) char smem[];
    const uint32_t sb = smem_u32(smem);
    const int tid = threadIdx.x;
    const int lane = tid & 31;
    const int wid = tid >> 5;
    const int bn = blockIdx.x * 128;

    // ---- load B tiles (128 rows x 128 k, hi/lo), once per CTA ----
#pragma unroll
    for (int i = 0; i < 8; i++) {
        int idx = tid + i * 256;          // 0..2047
        int r = idx >> 4, c = idx & 15;
        int gn = bn + r;
        uint4 vh = make_uint4(0, 0, 0, 0), vl = make_uint4(0, 0, 0, 0);
        if (gn < V_DIM) {
            vh = *reinterpret_cast<const uint4*>(&g_nhi[(size_t)gn * E_DIM + c * 8]);
            vl = *reinterpret_cast<const uint4*>(&g_nlo[(size_t)gn * E_DIM + c * 8]);
        }
        uint32_t off = (uint32_t)((r << 8) + ((c ^ (r & 7)) << 4));
        *reinterpret_cast<uint4*>(smem + OFF_BHI + off) = vh;
        *reinterpret_cast<uint4*>(smem + OFF_BLO + off) = vl;
    }

    const int wm = (wid >> 2) * 32;
    const int wn = (wid & 3) * 32;

    // per-thread ldmatrix address precompute
    const int i8  = lane & 7;
    const int q   = lane >> 3;           // 0..3
    const int qhi = q >> 1;              // A: k-chunk-half select
    const int q2  = q & 1;               // k-chunk-half select
    uint32_t a_rowoff[2];
    int a7[2];
#pragma unroll
    for (int mf = 0; mf < 2; mf++) {
        int ar = wm + mf * 16 + i8 + ((q & 1) << 3);
        a_rowoff[mf] = (uint32_t)(ar << 8);
        a7[mf] = ar & 7;
    }
    // B: nf-pair packing — lanes 16-31 load the second nf of the pair
    uint32_t b_rowoff[2];
    int b7[2];
#pragma unroll
    for (int p = 0; p < 2; p++) {
        int br = wn + (p * 2 + (lane >> 4)) * 8 + i8;
        b_rowoff[p] = (uint32_t)(br << 8);
        b7[p] = br & 7;
    }

    // epilogue constants
    const int r_in = lane >> 2;          // 0..7
    const int cp   = lane & 3;           // col-pair
    const int wni  = wid & 3;
    float* smax = (float*)(smem + OFF_SMAX);   // [64][4]
    float* ssum = (float*)(smem + OFF_SSUM);   // [64][4]
    bool cv[4][2];
#pragma unroll
    for (int nf = 0; nf < 4; nf++)
#pragma unroll
        for (int j = 0; j < 2; j++)
            cv[nf][j] = (bn + wn + nf * 8 + cp * 2 + j) < V_DIM;

    for (int mt = 0; mt < 4; mt++) {
        const int bm = (blockIdx.y * 4 + mt) * 64;

        // ---- load A tiles (64 rows x 128 k, hi/lo) ----
#pragma unroll
        for (int i = 0; i < 4; i++) {
            int idx = tid + i * 256;          // 0..1023
            int r = idx >> 4, c = idx & 15;
            uint32_t off = (uint32_t)((r << 8) + ((c ^ (r & 7)) << 4));
            *reinterpret_cast<uint4*>(smem + OFF_AHI + off) =
                *reinterpret_cast<const uint4*>(&g_qhi[(size_t)(bm + r) * E_DIM + c * 8]);
            *reinterpret_cast<uint4*>(smem + OFF_ALO + off) =
                *reinterpret_cast<const uint4*>(&g_qlo[(size_t)(bm + r) * E_DIM + c * 8]);
        }
        __syncthreads();

        float acc[2][4][4];
#pragma unroll
        for (int mf = 0; mf < 2; mf++)
#pragma unroll
            for (int nf = 0; nf < 4; nf++)
#pragma unroll
                for (int k = 0; k < 4; k++) acc[mf][nf][k] = 0.0f;

        // ---- mainloop: 8 LDSM + 24 HMMA per kk ----
#pragma unroll
        for (int kk = 0; kk < 8; kk++) {
            uint32_t ah[2][4], al[2][4];
#pragma unroll
            for (int mf = 0; mf < 2; mf++) {
                uint32_t chunk = (uint32_t)(((kk * 2 + qhi) ^ a7[mf]) << 4);
                ldmatrix_x4(ah[mf], sb + OFF_AHI + a_rowoff[mf] + chunk);
                ldmatrix_x4(al[mf], sb + OFF_ALO + a_rowoff[mf] + chunk);
            }
            uint32_t bh[4][2], bl[4][2];
#pragma unroll
            for (int p = 0; p < 2; p++) {
                uint32_t chunk = (uint32_t)(((kk * 2 + q2) ^ b7[p]) << 4);
                uint32_t th[4], tl[4];
                ldmatrix_x4(th, sb + OFF_BHI + b_rowoff[p] + chunk);
                ldmatrix_x4(tl, sb + OFF_BLO + b_rowoff[p] + chunk);
                bh[p * 2 + 0][0] = th[0]; bh[p * 2 + 0][1] = th[1];
                bh[p * 2 + 1][0] = th[2]; bh[p * 2 + 1][1] = th[3];
                bl[p * 2 + 0][0] = tl[0]; bl[p * 2 + 0][1] = tl[1];
                bl[p * 2 + 1][0] = tl[2]; bl[p * 2 + 1][1] = tl[3];
            }
            // term 1: Ahi * Bhi
#pragma unroll
            for (int mf = 0; mf < 2; mf++)
#pragma unroll
                for (int nf = 0; nf < 4; nf++)
                    mma16816(acc[mf][nf], ah[mf], bh[nf]);
            // term 2: Alo * Bhi
#pragma unroll
            for (int mf = 0; mf < 2; mf++)
#pragma unroll
                for (int nf = 0; nf < 4; nf++)
                    mma16816(acc[mf][nf], al[mf], bh[nf]);
            // term 3: Ahi * Blo
#pragma unroll
            for (int mf = 0; mf < 2; mf++)
#pragma unroll
                for (int nf = 0; nf < 4; nf++)
                    mma16816(acc[mf][nf], ah[mf], bl[nf]);
        }

        // ---- epilogue: store C (streaming, scalar: V_DIM odd) + partial LSE ----
#pragma unroll
        for (int mf = 0; mf < 2; mf++) {
#pragma unroll
            for (int h = 0; h < 2; h++) {
                int tr  = wm + mf * 16 + h * 8 + r_in;       // tile row 0..63
                int row = bm + tr;
                float m = -INFINITY;
                const size_t rowbase = (size_t)row * V_DIM;
#pragma unroll
                for (int nf = 0; nf < 4; nf++) {
                    float v0 = acc[mf][nf][h * 2 + 0];
                    float v1 = acc[mf][nf][h * 2 + 1];
                    int col = bn + wn + nf * 8 + cp * 2;
                    if (cv[nf][0]) { __stcs(&C[rowbase + col], v0);     m = fmaxf(m, v0); }
                    if (cv[nf][1]) { __stcs(&C[rowbase + col + 1], v1); m = fmaxf(m, v1); }
                }
                m = fmaxf(m, __shfl_xor_sync(0xFFFFFFFF, m, 1));
                m = fmaxf(m, __shfl_xor_sync(0xFFFFFFFF, m, 2));
                if (cp == 0) smax[tr * 4 + wni] = m;
            }
        }
        __syncthreads();

#pragma unroll
        for (int mf = 0; mf < 2; mf++) {
#pragma unroll
            for (int h = 0; h < 2; h++) {
                int tr = wm + mf * 16 + h * 8 + r_in;
                float g = fmaxf(fmaxf(smax[tr * 4 + 0], smax[tr * 4 + 1]),
                                fmaxf(smax[tr * 4 + 2], smax[tr * 4 + 3]));
                float s = 0.0f;
#pragma unroll
                for (int nf = 0; nf < 4; nf++) {
                    if (cv[nf][0]) s += __expf(acc[mf][nf][h * 2 + 0] - g);
                    if (cv[nf][1]) s += __expf(acc[mf][nf][h * 2 + 1] - g);
                }
                s += __shfl_xor_sync(0xFFFFFFFF, s, 1);
                s += __shfl_xor_sync(0xFFFFFFFF, s, 2);
                if (cp == 0) ssum[tr * 4 + wni] = s;
            }
        }
        __syncthreads();

        if (tid < 64) {
            float g = fmaxf(fmaxf(smax[tid * 4 + 0], smax[tid * 4 + 1]),
                            fmaxf(smax[tid * 4 + 2], smax[tid * 4 + 3]));
            float s = ssum[tid * 4 + 0] + ssum[tid * 4 + 1] +
                      ssum[tid * 4 + 2] + ssum[tid * 4 + 3];
            g_pmax[(size_t)(bm + tid) * NB + blockIdx.x] = g;
            g_psum[(size_t)(bm + tid) * NB + blockIdx.x] = s;
        }
        __syncthreads();
    }
}

// ---------------------------------------------------------------------------
// Kernel 5: reduce partial (max,sum) -> lse per row
// ---------------------------------------------------------------------------
__global__ void reduce_lse_kernel() {
    int b = blockIdx.x;
    int t = threadIdx.x;        // 128
    float m = -INFINITY, s = 0.0f;
    for (int i = t; i < NB; i += 128) {
        float pm = g_pmax[(size_t)b * NB + i];
        float ps = g_psum[(size_t)b * NB + i];
        if (pm > m) { s = s * __expf(m - pm) + ps; m = pm; }
        else        { s += ps * __expf(pm - m); }
    }
#pragma unroll
    for (int o = 16; o > 0; o >>= 1) {
        float m2 = __shfl_xor_sync(0xFFFFFFFF, m, o);
        float s2 = __shfl_xor_sync(0xFFFFFFFF, s, o);
        float M = fmaxf(m, m2);
        s = s * __expf(m - M) + s2 * __expf(m2 - M);
        m = M;
    }
    __shared__ float sm[4], ss[4];
    if ((t & 31) == 0) { sm[t >> 5] = m; ss[t >> 5] = s; }
    __syncthreads();
    if (t == 0) {
        m = sm[0]; s = ss[0];
#pragma unroll
        for (int w = 1; w < 4; w++) {
            float M = fmaxf(m, sm[w]);
            s = s * __expf(m - M) + ss[w] * __expf(sm[w] - M);
            m = M;
        }
        g_lse[b] = m + logf(s);
    }
}

// ---------------------------------------------------------------------------
// Kernel 6: out -= lse[row]  (flat float4, streaming)
// ---------------------------------------------------------------------------
__global__ void sub_lse_kernel(float4* __restrict__ C) {
    unsigned i = blockIdx.x * 256u + threadIdx.x;   // < N4
    float4 v = __ldcs(&C[i]);
    unsigned base = i * 4u;
    v.x -= g_lse[ base      / V_DIM];
    v.y -= g_lse[(base + 1) / V_DIM];
    v.z -= g_lse[(base + 2) / V_DIM];
    v.w -= g_lse[(base + 3) / V_DIM];
    __stcs(&C[i], v);
}

// ---------------------------------------------------------------------------
extern "C" void kernel_launch(void* const* d_in, const int* in_sizes, int n_in,
                              void* d_out, int out_size) {
    const float* xs     = (const float*)d_in[0];
    const float* metric = (const float*)d_in[1];
    const float* EMBEDM = (const float*)d_in[2];
    const float* NEG    = (const float*)d_in[3];
    float* out = (float*)d_out;

    cudaFuncSetAttribute(gemm_hmma_kernel,
                         cudaFuncAttributeMaxDynamicSharedMemorySize, SMEM_TOTAL);

    find_ids_kernel<<<N4 / 256, 256>>>((const float4*)xs);
    gather_project_kernel<<<B_DIM, E_DIM>>>(EMBEDM, metric);
    convert_neg_kernel<<<(V_DIM * E_DIM + 255) / 256, 256>>>(NEG);

    gemm_hmma_kernel<<<dim3(NB, 4), 256, SMEM_TOTAL>>>(out);

    reduce_lse_kernel<<<B_DIM, 128>>>();
    sub_lse_kernel<<<N4 / 256, 256>>>((float4*)out);
}